// round 15
// baseline (speedup 1.0000x reference)
#include <cuda_runtime.h>
#include <cuda_bf16.h>

#define BB 64      // batch
#define SS 512     // seq len
#define DD 768     // input dim
#define HH 512     // hidden
#define TT 21      // tags
#define G4 2048    // 4*H
#define H2 1024    // 2*H
#define NBLK_DIR 64   // persistent blocks per direction (barrier group)

// ---------------- scratch (device globals; no allocation allowed) ------------
__device__ float g_pre[(size_t)2 * SS * BB * G4];   // [dir][s][b][4H]
__device__ float g_h[(size_t)SS * BB * H2];          // [s][b][2H] (fwd | bwd)
__device__ float g_hT[(size_t)SS * H2 * BB];         // [s][k(2H)][b] transposed mirror
__device__ float g_emis[(size_t)SS * BB * TT];       // [s][b][T]
__device__ unsigned char g_hist[(size_t)BB * SS * TT]; // viterbi backtrace

// per-direction grid barrier state
__device__ unsigned g_cnt[2] = {0, 0};
__device__ volatile unsigned g_gend[2] = {0, 0};

__device__ __forceinline__ void gbar_dir(int dir) {
    __syncthreads();
    if (threadIdx.x == 0) {
        __threadfence();
        unsigned my = g_gend[dir];
        if (atomicAdd(&g_cnt[dir], 1) == NBLK_DIR - 1) {
            g_cnt[dir] = 0;
            __threadfence();
            g_gend[dir] = my + 1;
        } else {
            while (g_gend[dir] == my) { }
        }
        __threadfence();
    }
    __syncthreads();
}

__device__ __forceinline__ float4 ldcg4(const float* p) {
    return __ldcg((const float4*)p);
}

// =============================================================================
// 1) Pre-GEMM (R13-verified): 128x128 tile, 8x8 micro, float4, double-buffered
// =============================================================================
__global__ __launch_bounds__(256, 2) void k_pre2(
    const float* __restrict__ x,
    const float* __restrict__ Wf, const float* __restrict__ bf,
    const float* __restrict__ Wb, const float* __restrict__ bbv)
{
    const int dir = blockIdx.z;
    const float* __restrict__ W    = dir ? Wb : Wf;
    const float* __restrict__ bias = dir ? bbv : bf;
    const int m0 = blockIdx.y * 128;
    const int n0 = blockIdx.x * 128;

    __shared__ __align__(16) float As[2][8][128];
    __shared__ __align__(16) float Bs[2][8][128];

    const int tid = threadIdx.x;
    const int tx = tid & 15;
    const int ty = tid >> 4;
    const int lrow = tid >> 1;
    const int lk   = (tid & 1) * 4;

    const float* Aptr = x + (size_t)(m0 + lrow) * DD + lk;
    const float* Bptr = W + (size_t)(n0 + lrow) * DD + lk;

    float acc[8][8];
#pragma unroll
    for (int i = 0; i < 8; i++)
#pragma unroll
        for (int j = 0; j < 8; j++) acc[i][j] = 0.f;

    {
        float4 av = *(const float4*)Aptr;
        float4 bv = *(const float4*)Bptr;
        As[0][lk + 0][lrow] = av.x; As[0][lk + 1][lrow] = av.y;
        As[0][lk + 2][lrow] = av.z; As[0][lk + 3][lrow] = av.w;
        Bs[0][lk + 0][lrow] = bv.x; Bs[0][lk + 1][lrow] = bv.y;
        Bs[0][lk + 2][lrow] = bv.z; Bs[0][lk + 3][lrow] = bv.w;
    }
    __syncthreads();

#pragma unroll 1
    for (int c = 0; c < 96; c++) {
        const int cur = c & 1;
        float4 nav, nbv;
        if (c < 95) {
            nav = *(const float4*)(Aptr + (c + 1) * 8);
            nbv = *(const float4*)(Bptr + (c + 1) * 8);
        }
#pragma unroll
        for (int k = 0; k < 8; k++) {
            float4 a0 = *(const float4*)&As[cur][k][ty * 8];
            float4 a1 = *(const float4*)&As[cur][k][ty * 8 + 4];
            float4 b0 = *(const float4*)&Bs[cur][k][tx * 8];
            float4 b1 = *(const float4*)&Bs[cur][k][tx * 8 + 4];
            float aa[8]  = {a0.x, a0.y, a0.z, a0.w, a1.x, a1.y, a1.z, a1.w};
            float bb2[8] = {b0.x, b0.y, b0.z, b0.w, b1.x, b1.y, b1.z, b1.w};
#pragma unroll
            for (int i = 0; i < 8; i++)
#pragma unroll
                for (int j = 0; j < 8; j++) acc[i][j] += aa[i] * bb2[j];
        }
        if (c < 95) {
            const int nxt = cur ^ 1;
            As[nxt][lk + 0][lrow] = nav.x; As[nxt][lk + 1][lrow] = nav.y;
            As[nxt][lk + 2][lrow] = nav.z; As[nxt][lk + 3][lrow] = nav.w;
            Bs[nxt][lk + 0][lrow] = nbv.x; Bs[nxt][lk + 1][lrow] = nbv.y;
            Bs[nxt][lk + 2][lrow] = nbv.z; Bs[nxt][lk + 3][lrow] = nbv.w;
        }
        __syncthreads();
    }

#pragma unroll
    for (int i = 0; i < 8; i++) {
        const int m = m0 + ty * 8 + i;
        const int b = m >> 9, s = m & 511;
        float* Crow = g_pre + (((size_t)dir * SS + s) * BB + b) * G4;
#pragma unroll
        for (int j = 0; j < 8; j++) {
            const int n = n0 + tx * 8 + j;
            Crow[n] = acc[i][j] + bias[n];
        }
    }
}

// =============================================================================
// 2) Persistent recurrence v4: chunk-pipelined staging + pre-prefetch.
//    128 blocks (dir = bid>>6, j0 = (bid&63)*8), 512 threads.
//    Thread map: tx = tid&31 (col c = gate*8+jj), ty = tid>>5 (4-batch group).
//    All threads sweep k 0..511 in 8 chunks of 64; chunk c+1 is LDG'd into
//    registers while chunk c is FMA'd (hs double-buffered, 16 KB each).
// =============================================================================
#define RSM_W  (512 * 32)          // Wsm [k][c]        64 KB
#define RSM_H  (2 * 64 * 64)       // hs  [buf][kk][b]  32 KB
#define RSM_G  (64 * 33)           // gsm [b][c]        8.4 KB
#define RSM_C  (64 * 8)            // csm [b][jj]       2 KB
#define SMEM_REC_BYTES ((RSM_W + RSM_H + RSM_G + RSM_C) * 4)

__global__ __launch_bounds__(512) void k_rec(
    const float* __restrict__ Whf, const float* __restrict__ Whb)
{
    extern __shared__ __align__(16) float sm[];
    float* Wsm = sm;                 // [k][32]
    float* hs  = Wsm + RSM_W;        // [2][64*64]
    float* gsm = hs + RSM_H;         // [64][33]
    float* csm = gsm + RSM_G;        // [64][8]

    const int bid  = blockIdx.x;
    const int dir  = bid >> 6;
    const int j0   = (bid & 63) * 8;
    const int tid  = threadIdx.x;            // 0..511
    const int tx   = tid & 31;               // col c = gate*8 + jj
    const int ty   = tid >> 5;               // 0..15, batches ty*4..ty*4+3
    const int dirH = dir * HH;
    const float* __restrict__ Whh = dir ? Whb : Whf;

    // cell-phase coordinates (fixed)
    const int cb  = tid >> 3;                // batch 0..63
    const int cjj = tid & 7;                 // jj 0..7

    // ---- load Whh slice once: Wsm[k][c] ----
    {
        const int c = tid >> 4;                       // 0..31
        const int n = (c >> 3) * HH + j0 + (c & 7);   // weight row
        const float* wrow = Whh + (size_t)n * HH;
        const int ks = (tid & 15) * 32;               // 32 consecutive k
#pragma unroll
        for (int q = 0; q < 8; q++) {
            float4 v = *(const float4*)(wrow + ks + q * 4);
            Wsm[(ks + q * 4 + 0) * 32 + c] = v.x;
            Wsm[(ks + q * 4 + 1) * 32 + c] = v.y;
            Wsm[(ks + q * 4 + 2) * 32 + c] = v.z;
            Wsm[(ks + q * 4 + 3) * 32 + c] = v.w;
        }
    }
    __syncthreads();

    for (int t = 0; t < SS; t++) {
        const int tpos = dir ? (SS - 1 - t) : t;

        // ---- prefetch this thread's pre-gate values (hide DRAM latency) ----
        const float* pre = g_pre + (((size_t)dir * SS + tpos) * BB + cb) * G4;
        float pg0 = pre[j0 + cjj];
        float pg1 = pre[HH + j0 + cjj];
        float pg2 = pre[2 * HH + j0 + cjj];
        float pg3 = pre[3 * HH + j0 + cjj];

        float acc[4] = {0.f, 0.f, 0.f, 0.f};

        if (t > 0) {
            const int tprev = dir ? (tpos + 1) : (tpos - 1);
            // h^T slice for this dir: [512 k][64 b] contiguous
            const float* src = g_hT + ((size_t)tprev * H2 + dirH) * 64;

            // prologue: chunk 0 -> buf 0 (1024 float4; 2 per thread)
            float4 r0 = ldcg4(src + (size_t)tid * 4);
            float4 r1 = ldcg4(src + (size_t)(tid + 512) * 4);
            *(float4*)(hs + (size_t)tid * 4)         = r0;
            *(float4*)(hs + (size_t)(tid + 512) * 4) = r1;
            __syncthreads();

#pragma unroll 1
            for (int c = 0; c < 8; c++) {
                const int buf = c & 1;
                float4 n0, n1;
                if (c < 7) {   // prefetch chunk c+1 into registers
                    const float* s2 = src + (size_t)(c + 1) * 4096;
                    n0 = ldcg4(s2 + (size_t)tid * 4);
                    n1 = ldcg4(s2 + (size_t)(tid + 512) * 4);
                }
                // FMA over this chunk's 64 k
                const float* hb = hs + buf * 4096 + ty * 4;
                const float* wb = Wsm + (c * 64) * 32 + tx;
#pragma unroll 16
                for (int kk = 0; kk < 64; kk++) {
                    const float bv = wb[kk * 32];
                    float4 a = *(const float4*)(hb + kk * 64);
                    acc[0] += a.x * bv;
                    acc[1] += a.y * bv;
                    acc[2] += a.z * bv;
                    acc[3] += a.w * bv;
                }
                if (c < 7) {   // stage chunk c+1 into the other buffer
                    float* d2 = hs + (buf ^ 1) * 4096;
                    *(float4*)(d2 + (size_t)tid * 4)         = n0;
                    *(float4*)(d2 + (size_t)(tid + 512) * 4) = n1;
                    __syncthreads();
                }
            }

            // stage gate tile: gsm[b][c]
#pragma unroll
            for (int i = 0; i < 4; i++)
                gsm[(ty * 4 + i) * 33 + tx] = acc[i];
        }
        __syncthreads();

        // ---- fused cell update: 512 (b,jj) pairs, 1 per thread ----
        {
            float gi = pg0, gf = pg1, gg = pg2, go = pg3;
            float cp = 0.f;
            if (t > 0) {
                const int g0 = cb * 33;
                gi += gsm[g0 + cjj];
                gf += gsm[g0 + 8 + cjj];
                gg += gsm[g0 + 16 + cjj];
                go += gsm[g0 + 24 + cjj];
                cp = csm[cb * 8 + cjj];
            }
            float iv = 1.f / (1.f + expf(-gi));
            float fv = 1.f / (1.f + expf(-gf));
            float gv = tanhf(gg);
            float ov = 1.f / (1.f + expf(-go));
            float cn = fv * cp + iv * gv;
            csm[cb * 8 + cjj] = cn;
            float hv = ov * tanhf(cn);
            g_h[((size_t)tpos * BB + cb) * H2 + dirH + j0 + cjj] = hv;
            g_hT[((size_t)tpos * H2 + dirH + j0 + cjj) * 64 + cb] = hv;
        }
        gbar_dir(dir);   // h(tpos) + hT(tpos) visible before next step
    }
}

// =============================================================================
// 3) Emissions (verified scalar GEMM core, unchanged)
// =============================================================================
__device__ __forceinline__ void gemm_core(
    const float* __restrict__ A, int lda,
    const float* __restrict__ Bw, int ldb,
    float* __restrict__ C, int ldc,
    const float* __restrict__ bias,
    int K, int n0, int N)
{
    __shared__ float sA[16][65];
    __shared__ float sB[16][65];

    const int tid = threadIdx.x;
    const int tx = tid & 15;
    const int ty = tid >> 4;

    float acc[4][4];
#pragma unroll
    for (int i = 0; i < 4; i++)
#pragma unroll
        for (int j = 0; j < 4; j++) acc[i][j] = 0.f;

    for (int k0 = 0; k0 < K; k0 += 16) {
#pragma unroll
        for (int r = 0; r < 4; r++) {
            int idx = tid + r * 256;
            int k  = idx & 15;
            int mn = idx >> 4;
            sA[k][mn] = A[(size_t)mn * lda + k0 + k];
            int n = n0 + mn;
            sB[k][mn] = (n < N) ? Bw[(size_t)n * ldb + k0 + k] : 0.f;
        }
        __syncthreads();
#pragma unroll
        for (int k = 0; k < 16; k++) {
            float a0 = sA[k][ty * 4 + 0];
            float a1 = sA[k][ty * 4 + 1];
            float a2 = sA[k][ty * 4 + 2];
            float a3 = sA[k][ty * 4 + 3];
            float b0 = sB[k][tx * 4 + 0];
            float b1 = sB[k][tx * 4 + 1];
            float b2 = sB[k][tx * 4 + 2];
            float b3 = sB[k][tx * 4 + 3];
            acc[0][0] += a0 * b0; acc[0][1] += a0 * b1; acc[0][2] += a0 * b2; acc[0][3] += a0 * b3;
            acc[1][0] += a1 * b0; acc[1][1] += a1 * b1; acc[1][2] += a1 * b2; acc[1][3] += a1 * b3;
            acc[2][0] += a2 * b0; acc[2][1] += a2 * b1; acc[2][2] += a2 * b2; acc[2][3] += a2 * b3;
            acc[3][0] += a3 * b0; acc[3][1] += a3 * b1; acc[3][2] += a3 * b2; acc[3][3] += a3 * b3;
        }
        __syncthreads();
    }

#pragma unroll
    for (int i = 0; i < 4; i++) {
        int m = ty * 4 + i;
#pragma unroll
        for (int j = 0; j < 4; j++) {
            int n = n0 + tx * 4 + j;
            if (n < N)
                C[(size_t)m * ldc + n] = acc[i][j] + (bias ? bias[n] : 0.f);
        }
    }
}

__global__ __launch_bounds__(256) void k_emisg(
    const float* __restrict__ Wout, const float* __restrict__ bout)
{
    int s = blockIdx.y;
    const float* A = g_h + (size_t)s * BB * H2;
    float* C = g_emis + (size_t)s * BB * TT;
    gemm_core(A, H2, Wout, H2, C, TT, bout, H2, 0, TT);
}

// ---- Viterbi (verified): one thread per batch, float output
__global__ __launch_bounds__(32) void k_vit_naive(
    const int* __restrict__ mask,
    const float* __restrict__ trans,
    const float* __restrict__ startT,
    const float* __restrict__ endT,
    float* __restrict__ out)
{
    const int b = blockIdx.x * 32 + threadIdx.x;
    if (b >= BB) return;

    float sc[TT];
    float ns[TT];
    unsigned char* hist = g_hist + (size_t)b * SS * TT;

    for (int n = 0; n < TT; n++)
        sc[n] = startT[n] + g_emis[(size_t)b * TT + n];

    for (int t = 1; t < SS; t++) {
        const int m = mask[b * SS + t];
        for (int n = 0; n < TT; n++) {
            float best = -3.4e38f; int arg = 0;
            for (int p = 0; p < TT; p++) {
                float v = sc[p] + trans[p * TT + n];
                if (v > best) { best = v; arg = p; }
            }
            ns[n] = best + g_emis[((size_t)t * BB + b) * TT + n];
            hist[(size_t)(t - 1) * TT + n] = m ? (unsigned char)arg
                                               : (unsigned char)0;
        }
        if (m)
            for (int n = 0; n < TT; n++) sc[n] = ns[n];
    }

    float best = -3.4e38f; int last = 0;
    for (int n = 0; n < TT; n++) {
        float v = sc[n] + endT[n];
        if (v > best) { best = v; last = n; }
    }

    out[b * SS + SS - 1] = (float)last;
    int cur = last;
    for (int t = SS - 2; t >= 0; t--) {
        cur = hist[(size_t)t * TT + cur];
        out[b * SS + t] = (float)cur;
    }
}

// =============================================================================
// Host (verified input mapper)
// =============================================================================
extern "C" void kernel_launch(void* const* d_in, const int* in_sizes, int n_in,
                              void* d_out, int out_size) {
    const long long SZ_X = (long long)BB * SS * DD;
    const long long SZ_MASK = (long long)BB * SS;
    const long long SZ_WIH = (long long)G4 * DD;
    const long long SZ_WHH = (long long)G4 * HH;
    const long long SZ_B4 = G4;
    const long long SZ_WOUT = (long long)TT * H2;
    const long long SZ_T21 = TT;
    const long long SZ_TR = (long long)TT * TT;

    int ix = -1, imask = -1, iwout = -1, itr = -1;
    int wih[2] = {-1, -1}, whh[2] = {-1, -1}, b4[2] = {-1, -1};
    int t21[3] = {-1, -1, -1};
    int nwih = 0, nwhh = 0, nb4 = 0, nt21 = 0;

    for (int scale_pass = 0; scale_pass < 2 && ix < 0; scale_pass++) {
        const long long mul = scale_pass ? 4 : 1;
        ix = imask = iwout = itr = -1;
        nwih = nwhh = nb4 = nt21 = 0;
        for (int i = 0; i < n_in; i++) {
            long long sz = (long long)in_sizes[i];
            if      (sz == SZ_X * mul)    ix = i;
            else if (sz == SZ_MASK * mul) imask = i;
            else if (sz == SZ_WOUT * mul) iwout = i;
            else if (sz == SZ_TR * mul)   itr = i;
            else if (sz == SZ_WIH * mul && nwih < 2) wih[nwih++] = i;
            else if (sz == SZ_WHH * mul && nwhh < 2) whh[nwhh++] = i;
            else if (sz == SZ_B4 * mul && nb4 < 2)   b4[nb4++] = i;
            else if (sz == SZ_T21 * mul && nt21 < 3) t21[nt21++] = i;
        }
    }

    const bool alpha = (ix == n_in - 1);
    const int iWihf = alpha ? wih[1] : wih[0];
    const int iWihb = alpha ? wih[0] : wih[1];
    const int iWhhf = alpha ? whh[1] : whh[0];
    const int iWhhb = alpha ? whh[0] : whh[1];
    const int ibf   = alpha ? b4[1] : b4[0];
    const int ibb   = alpha ? b4[0] : b4[1];
    const int ibout = t21[0];
    const int ist   = alpha ? t21[2] : t21[1];
    const int ien   = alpha ? t21[1] : t21[2];

    const float* x      = (const float*)d_in[ix];
    const int*   mask   = (const int*)  d_in[imask];
    const float* Wih_f  = (const float*)d_in[iWihf];
    const float* Whh_f  = (const float*)d_in[iWhhf];
    const float* b_f    = (const float*)d_in[ibf];
    const float* Wih_b  = (const float*)d_in[iWihb];
    const float* Whh_b  = (const float*)d_in[iWhhb];
    const float* b_b    = (const float*)d_in[ibb];
    const float* W_out  = (const float*)d_in[iwout];
    const float* b_out  = (const float*)d_in[ibout];
    const float* trans  = (const float*)d_in[itr];
    const float* startT = (const float*)d_in[ist];
    const float* endT   = (const float*)d_in[ien];
    float* out = (float*)d_out;

    cudaFuncSetAttribute(k_rec, cudaFuncAttributeMaxDynamicSharedMemorySize,
                         SMEM_REC_BYTES);

    // 1) input projections (float4 128x128 GEMM)               (1 node)
    k_pre2<<<dim3(G4 / 128, 256, 2), 256>>>(x, Wih_f, b_f, Wih_b, b_b);
    // 2) recurrence: persistent v4, pipelined chunks           (1 node)
    k_rec<<<2 * NBLK_DIR, 512, SMEM_REC_BYTES>>>(Whh_f, Whh_b);
    // 3) emissions                                             (1 node)
    k_emisg<<<dim3(1, SS), 256>>>(W_out, b_out);
    // 4) viterbi (float output)                                (1 node)
    k_vit_naive<<<2, 32>>>(mask, trans, startT, endT, out);
    // total 4 graph nodes.
}

// round 17
// speedup vs baseline: 1.2161x; 1.2161x over previous
#include <cuda_runtime.h>
#include <cuda_bf16.h>

#define BB 64      // batch
#define SS 512     // seq len
#define DD 768     // input dim
#define HH 512     // hidden
#define TT 21      // tags
#define G4 2048    // 4*H
#define H2 1024    // 2*H
#define NBLK_DIR 64   // persistent blocks per direction (barrier group)

// ---------------- scratch (device globals; no allocation allowed) ------------
__device__ float g_pre[(size_t)2 * SS * BB * G4];   // [dir][s][b][4H]
__device__ float g_h[(size_t)SS * BB * H2];          // [s][b][2H] (fwd | bwd)
__device__ float g_hT[(size_t)SS * H2 * BB];         // [s][k(2H)][b] transposed mirror
__device__ float g_emis[(size_t)SS * BB * TT];       // [s][b][T]
__device__ unsigned char g_hist[(size_t)BB * SS * TT]; // viterbi backtrace

// per-direction grid barrier state
__device__ unsigned g_cnt[2] = {0, 0};
__device__ volatile unsigned g_gend[2] = {0, 0};

__device__ __forceinline__ void gbar_dir(int dir) {
    __syncthreads();
    if (threadIdx.x == 0) {
        __threadfence();
        unsigned my = g_gend[dir];
        if (atomicAdd(&g_cnt[dir], 1) == NBLK_DIR - 1) {
            g_cnt[dir] = 0;
            __threadfence();
            g_gend[dir] = my + 1;
        } else {
            while (g_gend[dir] == my) { }
        }
        __threadfence();
    }
    __syncthreads();
}

__device__ __forceinline__ float4 ldcg4(const float* p) {
    return __ldcg((const float4*)p);
}

// =============================================================================
// 1) Pre-GEMM (R13-verified): 128x128 tile, 8x8 micro, float4, double-buffered
// =============================================================================
__global__ __launch_bounds__(256, 2) void k_pre2(
    const float* __restrict__ x,
    const float* __restrict__ Wf, const float* __restrict__ bf,
    const float* __restrict__ Wb, const float* __restrict__ bbv)
{
    const int dir = blockIdx.z;
    const float* __restrict__ W    = dir ? Wb : Wf;
    const float* __restrict__ bias = dir ? bbv : bf;
    const int m0 = blockIdx.y * 128;
    const int n0 = blockIdx.x * 128;

    __shared__ __align__(16) float As[2][8][128];
    __shared__ __align__(16) float Bs[2][8][128];

    const int tid = threadIdx.x;
    const int tx = tid & 15;
    const int ty = tid >> 4;
    const int lrow = tid >> 1;
    const int lk   = (tid & 1) * 4;

    const float* Aptr = x + (size_t)(m0 + lrow) * DD + lk;
    const float* Bptr = W + (size_t)(n0 + lrow) * DD + lk;

    float acc[8][8];
#pragma unroll
    for (int i = 0; i < 8; i++)
#pragma unroll
        for (int j = 0; j < 8; j++) acc[i][j] = 0.f;

    {
        float4 av = *(const float4*)Aptr;
        float4 bv = *(const float4*)Bptr;
        As[0][lk + 0][lrow] = av.x; As[0][lk + 1][lrow] = av.y;
        As[0][lk + 2][lrow] = av.z; As[0][lk + 3][lrow] = av.w;
        Bs[0][lk + 0][lrow] = bv.x; Bs[0][lk + 1][lrow] = bv.y;
        Bs[0][lk + 2][lrow] = bv.z; Bs[0][lk + 3][lrow] = bv.w;
    }
    __syncthreads();

#pragma unroll 1
    for (int c = 0; c < 96; c++) {
        const int cur = c & 1;
        float4 nav, nbv;
        if (c < 95) {
            nav = *(const float4*)(Aptr + (c + 1) * 8);
            nbv = *(const float4*)(Bptr + (c + 1) * 8);
        }
#pragma unroll
        for (int k = 0; k < 8; k++) {
            float4 a0 = *(const float4*)&As[cur][k][ty * 8];
            float4 a1 = *(const float4*)&As[cur][k][ty * 8 + 4];
            float4 b0 = *(const float4*)&Bs[cur][k][tx * 8];
            float4 b1 = *(const float4*)&Bs[cur][k][tx * 8 + 4];
            float aa[8]  = {a0.x, a0.y, a0.z, a0.w, a1.x, a1.y, a1.z, a1.w};
            float bb2[8] = {b0.x, b0.y, b0.z, b0.w, b1.x, b1.y, b1.z, b1.w};
#pragma unroll
            for (int i = 0; i < 8; i++)
#pragma unroll
                for (int j = 0; j < 8; j++) acc[i][j] += aa[i] * bb2[j];
        }
        if (c < 95) {
            const int nxt = cur ^ 1;
            As[nxt][lk + 0][lrow] = nav.x; As[nxt][lk + 1][lrow] = nav.y;
            As[nxt][lk + 2][lrow] = nav.z; As[nxt][lk + 3][lrow] = nav.w;
            Bs[nxt][lk + 0][lrow] = nbv.x; Bs[nxt][lk + 1][lrow] = nbv.y;
            Bs[nxt][lk + 2][lrow] = nbv.z; Bs[nxt][lk + 3][lrow] = nbv.w;
        }
        __syncthreads();
    }

#pragma unroll
    for (int i = 0; i < 8; i++) {
        const int m = m0 + ty * 8 + i;
        const int b = m >> 9, s = m & 511;
        float* Crow = g_pre + (((size_t)dir * SS + s) * BB + b) * G4;
#pragma unroll
        for (int j = 0; j < 8; j++) {
            const int n = n0 + tx * 8 + j;
            Crow[n] = acc[i][j] + bias[n];
        }
    }
}

// =============================================================================
// 2) Persistent recurrence v5 = R14 v3 skeleton + 4b x 4c microtile FMA phase.
//    128 blocks (dir = bid>>6, j0 = (bid&63)*8), 512 threads.
//    Per step: single contiguous 128KB staging g_hT->smem (verified), then
//    4 k-groups x 128 threads, each thread 4b x 4c over 128 k
//    (2 x LDS.128 per k feeding 16 FMA = 2 B/FMA smem traffic),
//    4 gsm partials combined in the cell phase, per-dir grid barrier.
// =============================================================================
#define RSM_W  (512 * 32)          // Wsm [k][c]         64 KB
#define RSM_H  (512 * 64)          // hs  [k][b]        128 KB
#define RSM_G  (4 * 64 * 32)       // gsm [kg][b][c]     32 KB
#define RSM_C  (64 * 8)            // csm [b][jj]         2 KB
#define SMEM_REC_BYTES ((RSM_W + RSM_H + RSM_G + RSM_C) * 4)   // 226 KB

__global__ __launch_bounds__(512) void k_rec(
    const float* __restrict__ Whf, const float* __restrict__ Whb)
{
    extern __shared__ __align__(16) float sm[];
    float* Wsm = sm;                 // [k][32]
    float* hs  = Wsm + RSM_W;        // [k][64]
    float* gsm = hs + RSM_H;         // [4][64][32]
    float* csm = gsm + RSM_G;        // [64][8]

    const int bid  = blockIdx.x;
    const int dir  = bid >> 6;
    const int j0   = (bid & 63) * 8;
    const int tid  = threadIdx.x;            // 0..511
    const int dirH = dir * HH;
    const float* __restrict__ Whh = dir ? Whb : Whf;

    // FMA-phase coordinates: 4 k-groups of 128 threads; 4b x 4c microtile
    const int kg  = tid >> 7;                // 0..3
    const int loc = tid & 127;
    const int cg  = loc & 7;                 // c0 = cg*4 (cols)
    const int bg  = loc >> 3;                // 0..15, b0 = bg*4

    // cell-phase coordinates
    const int cb  = tid >> 3;                // batch 0..63
    const int cjj = tid & 7;                 // jj 0..7

    // ---- load Whh slice once: Wsm[k][c], c = gate*8 + jj (verified) ----
    {
        const int c = tid >> 4;                       // 0..31
        const int n = (c >> 3) * HH + j0 + (c & 7);   // weight row
        const float* wrow = Whh + (size_t)n * HH;
        const int ks = (tid & 15) * 32;               // 32 consecutive k
#pragma unroll
        for (int q = 0; q < 8; q++) {
            float4 v = *(const float4*)(wrow + ks + q * 4);
            Wsm[(ks + q * 4 + 0) * 32 + c] = v.x;
            Wsm[(ks + q * 4 + 1) * 32 + c] = v.y;
            Wsm[(ks + q * 4 + 2) * 32 + c] = v.z;
            Wsm[(ks + q * 4 + 3) * 32 + c] = v.w;
        }
    }
    __syncthreads();

    for (int t = 0; t < SS; t++) {
        const int tpos = dir ? (SS - 1 - t) : t;

        if (t > 0) {
            // ---- staging: contiguous copy of h^T slice (512 k x 64 b) ----
            const int tprev = dir ? (tpos + 1) : (tpos - 1);
            const float* src = g_hT + ((size_t)tprev * H2 + dirH) * 64;
#pragma unroll
            for (int j2 = 0; j2 < 16; j2++) {
                const int f = tid + 512 * j2;        // float4 index 0..8191
                float4 v = ldcg4(src + (size_t)f * 4);
                *(float4*)(hs + (size_t)f * 4) = v;
            }
            __syncthreads();

            // ---- FMA phase: 4b x 4c microtile over this group's 128 k ----
            float acc[4][4];
#pragma unroll
            for (int i = 0; i < 4; i++)
#pragma unroll
                for (int j = 0; j < 4; j++) acc[i][j] = 0.f;

            const float* hb = hs + bg * 4;
            const float* wb = Wsm + cg * 4;
            const int kbase = kg * 128;
#pragma unroll 8
            for (int kk = 0; kk < 128; kk++) {
                const int k = kbase + kk;
                float4 w = *(const float4*)&wb[k * 32];
                float4 a = *(const float4*)&hb[k * 64];
                acc[0][0] += a.x * w.x; acc[0][1] += a.x * w.y;
                acc[0][2] += a.x * w.z; acc[0][3] += a.x * w.w;
                acc[1][0] += a.y * w.x; acc[1][1] += a.y * w.y;
                acc[1][2] += a.y * w.z; acc[1][3] += a.y * w.w;
                acc[2][0] += a.z * w.x; acc[2][1] += a.z * w.y;
                acc[2][2] += a.z * w.z; acc[2][3] += a.z * w.w;
                acc[3][0] += a.w * w.x; acc[3][1] += a.w * w.y;
                acc[3][2] += a.w * w.z; acc[3][3] += a.w * w.w;
            }

            // stage partials: gsm[kg][b][c] (float4 per row)
#pragma unroll
            for (int i = 0; i < 4; i++) {
                float4 v = make_float4(acc[i][0], acc[i][1], acc[i][2], acc[i][3]);
                *(float4*)&gsm[kg * 2048 + (bg * 4 + i) * 32 + cg * 4] = v;
            }
        }
        __syncthreads();

        // ---- fused cell update: 512 (b,jj) pairs, 1 per thread ----
        {
            const float* pre = g_pre + (((size_t)dir * SS + tpos) * BB + cb) * G4;
            float gi = pre[j0 + cjj];
            float gf = pre[HH + j0 + cjj];
            float gg = pre[2 * HH + j0 + cjj];
            float go = pre[3 * HH + j0 + cjj];
            float cp = 0.f;
            if (t > 0) {
                const int g0 = cb * 32;
#pragma unroll
                for (int q = 0; q < 4; q++) {
                    const float* gq = gsm + q * 2048 + g0;
                    gi += gq[cjj];
                    gf += gq[8 + cjj];
                    gg += gq[16 + cjj];
                    go += gq[24 + cjj];
                }
                cp = csm[cb * 8 + cjj];
            }
            float iv = 1.f / (1.f + expf(-gi));
            float fv = 1.f / (1.f + expf(-gf));
            float gv = tanhf(gg);
            float ov = 1.f / (1.f + expf(-go));
            float cn = fv * cp + iv * gv;
            csm[cb * 8 + cjj] = cn;
            float hv = ov * tanhf(cn);
            g_h[((size_t)tpos * BB + cb) * H2 + dirH + j0 + cjj] = hv;
            g_hT[((size_t)tpos * H2 + dirH + j0 + cjj) * 64 + cb] = hv;
        }
        gbar_dir(dir);   // h(tpos) + hT(tpos) visible before next step
    }
}

// =============================================================================
// 3) Emissions (verified scalar GEMM core, unchanged)
// =============================================================================
__device__ __forceinline__ void gemm_core(
    const float* __restrict__ A, int lda,
    const float* __restrict__ Bw, int ldb,
    float* __restrict__ C, int ldc,
    const float* __restrict__ bias,
    int K, int n0, int N)
{
    __shared__ float sA[16][65];
    __shared__ float sB[16][65];

    const int tid = threadIdx.x;
    const int tx = tid & 15;
    const int ty = tid >> 4;

    float acc[4][4];
#pragma unroll
    for (int i = 0; i < 4; i++)
#pragma unroll
        for (int j = 0; j < 4; j++) acc[i][j] = 0.f;

    for (int k0 = 0; k0 < K; k0 += 16) {
#pragma unroll
        for (int r = 0; r < 4; r++) {
            int idx = tid + r * 256;
            int k  = idx & 15;
            int mn = idx >> 4;
            sA[k][mn] = A[(size_t)mn * lda + k0 + k];
            int n = n0 + mn;
            sB[k][mn] = (n < N) ? Bw[(size_t)n * ldb + k0 + k] : 0.f;
        }
        __syncthreads();
#pragma unroll
        for (int k = 0; k < 16; k++) {
            float a0 = sA[k][ty * 4 + 0];
            float a1 = sA[k][ty * 4 + 1];
            float a2 = sA[k][ty * 4 + 2];
            float a3 = sA[k][ty * 4 + 3];
            float b0 = sB[k][tx * 4 + 0];
            float b1 = sB[k][tx * 4 + 1];
            float b2 = sB[k][tx * 4 + 2];
            float b3 = sB[k][tx * 4 + 3];
            acc[0][0] += a0 * b0; acc[0][1] += a0 * b1; acc[0][2] += a0 * b2; acc[0][3] += a0 * b3;
            acc[1][0] += a1 * b0; acc[1][1] += a1 * b1; acc[1][2] += a1 * b2; acc[1][3] += a1 * b3;
            acc[2][0] += a2 * b0; acc[2][1] += a2 * b1; acc[2][2] += a2 * b2; acc[2][3] += a2 * b3;
            acc[3][0] += a3 * b0; acc[3][1] += a3 * b1; acc[3][2] += a3 * b2; acc[3][3] += a3 * b3;
        }
        __syncthreads();
    }

#pragma unroll
    for (int i = 0; i < 4; i++) {
        int m = ty * 4 + i;
#pragma unroll
        for (int j = 0; j < 4; j++) {
            int n = n0 + tx * 4 + j;
            if (n < N)
                C[(size_t)m * ldc + n] = acc[i][j] + (bias ? bias[n] : 0.f);
        }
    }
}

__global__ __launch_bounds__(256) void k_emisg(
    const float* __restrict__ Wout, const float* __restrict__ bout)
{
    int s = blockIdx.y;
    const float* A = g_h + (size_t)s * BB * H2;
    float* C = g_emis + (size_t)s * BB * TT;
    gemm_core(A, H2, Wout, H2, C, TT, bout, H2, 0, TT);
}

// ---- Viterbi (verified): one thread per batch, float output
__global__ __launch_bounds__(32) void k_vit_naive(
    const int* __restrict__ mask,
    const float* __restrict__ trans,
    const float* __restrict__ startT,
    const float* __restrict__ endT,
    float* __restrict__ out)
{
    const int b = blockIdx.x * 32 + threadIdx.x;
    if (b >= BB) return;

    float sc[TT];
    float ns[TT];
    unsigned char* hist = g_hist + (size_t)b * SS * TT;

    for (int n = 0; n < TT; n++)
        sc[n] = startT[n] + g_emis[(size_t)b * TT + n];

    for (int t = 1; t < SS; t++) {
        const int m = mask[b * SS + t];
        for (int n = 0; n < TT; n++) {
            float best = -3.4e38f; int arg = 0;
            for (int p = 0; p < TT; p++) {
                float v = sc[p] + trans[p * TT + n];
                if (v > best) { best = v; arg = p; }
            }
            ns[n] = best + g_emis[((size_t)t * BB + b) * TT + n];
            hist[(size_t)(t - 1) * TT + n] = m ? (unsigned char)arg
                                               : (unsigned char)0;
        }
        if (m)
            for (int n = 0; n < TT; n++) sc[n] = ns[n];
    }

    float best = -3.4e38f; int last = 0;
    for (int n = 0; n < TT; n++) {
        float v = sc[n] + endT[n];
        if (v > best) { best = v; last = n; }
    }

    out[b * SS + SS - 1] = (float)last;
    int cur = last;
    for (int t = SS - 2; t >= 0; t--) {
        cur = hist[(size_t)t * TT + cur];
        out[b * SS + t] = (float)cur;
    }
}

// =============================================================================
// Host (verified input mapper)
// =============================================================================
extern "C" void kernel_launch(void* const* d_in, const int* in_sizes, int n_in,
                              void* d_out, int out_size) {
    const long long SZ_X = (long long)BB * SS * DD;
    const long long SZ_MASK = (long long)BB * SS;
    const long long SZ_WIH = (long long)G4 * DD;
    const long long SZ_WHH = (long long)G4 * HH;
    const long long SZ_B4 = G4;
    const long long SZ_WOUT = (long long)TT * H2;
    const long long SZ_T21 = TT;
    const long long SZ_TR = (long long)TT * TT;

    int ix = -1, imask = -1, iwout = -1, itr = -1;
    int wih[2] = {-1, -1}, whh[2] = {-1, -1}, b4[2] = {-1, -1};
    int t21[3] = {-1, -1, -1};
    int nwih = 0, nwhh = 0, nb4 = 0, nt21 = 0;

    for (int scale_pass = 0; scale_pass < 2 && ix < 0; scale_pass++) {
        const long long mul = scale_pass ? 4 : 1;
        ix = imask = iwout = itr = -1;
        nwih = nwhh = nb4 = nt21 = 0;
        for (int i = 0; i < n_in; i++) {
            long long sz = (long long)in_sizes[i];
            if      (sz == SZ_X * mul)    ix = i;
            else if (sz == SZ_MASK * mul) imask = i;
            else if (sz == SZ_WOUT * mul) iwout = i;
            else if (sz == SZ_TR * mul)   itr = i;
            else if (sz == SZ_WIH * mul && nwih < 2) wih[nwih++] = i;
            else if (sz == SZ_WHH * mul && nwhh < 2) whh[nwhh++] = i;
            else if (sz == SZ_B4 * mul && nb4 < 2)   b4[nb4++] = i;
            else if (sz == SZ_T21 * mul && nt21 < 3) t21[nt21++] = i;
        }
    }

    const bool alpha = (ix == n_in - 1);
    const int iWihf = alpha ? wih[1] : wih[0];
    const int iWihb = alpha ? wih[0] : wih[1];
    const int iWhhf = alpha ? whh[1] : whh[0];
    const int iWhhb = alpha ? whh[0] : whh[1];
    const int ibf   = alpha ? b4[1] : b4[0];
    const int ibb   = alpha ? b4[0] : b4[1];
    const int ibout = t21[0];
    const int ist   = alpha ? t21[2] : t21[1];
    const int ien   = alpha ? t21[1] : t21[2];

    const float* x      = (const float*)d_in[ix];
    const int*   mask   = (const int*)  d_in[imask];
    const float* Wih_f  = (const float*)d_in[iWihf];
    const float* Whh_f  = (const float*)d_in[iWhhf];
    const float* b_f    = (const float*)d_in[ibf];
    const float* Wih_b  = (const float*)d_in[iWihb];
    const float* Whh_b  = (const float*)d_in[iWhhb];
    const float* b_b    = (const float*)d_in[ibb];
    const float* W_out  = (const float*)d_in[iwout];
    const float* b_out  = (const float*)d_in[ibout];
    const float* trans  = (const float*)d_in[itr];
    const float* startT = (const float*)d_in[ist];
    const float* endT   = (const float*)d_in[ien];
    float* out = (float*)d_out;

    cudaFuncSetAttribute(k_rec, cudaFuncAttributeMaxDynamicSharedMemorySize,
                         SMEM_REC_BYTES);

    // 1) input projections (float4 128x128 GEMM)               (1 node)
    k_pre2<<<dim3(G4 / 128, 256, 2), 256>>>(x, Wih_f, b_f, Wih_b, b_b);
    // 2) recurrence: persistent v5, 4bx4c microtile            (1 node)
    k_rec<<<2 * NBLK_DIR, 512, SMEM_REC_BYTES>>>(Whh_f, Whh_b);
    // 3) emissions                                             (1 node)
    k_emisg<<<dim3(1, SS), 256>>>(W_out, b_out);
    // 4) viterbi (float output)                                (1 node)
    k_vit_naive<<<2, 32>>>(mask, trans, startT, endT, out);
    // total 4 graph nodes.
}